// round 6
// baseline (speedup 1.0000x reference)
#include <cuda_runtime.h>
#include <cstdint>

// ---------------------------------------------------------------------------
// SCAConv decomposition (same math as R2-R4):
// out[b,o,l] = bias[o] + sum_i xu*kernel[o,i] + sum_i xu*b2[(l&31)*144+i]
//            + sum_j H[o*128+(l>>5), j] * G[b,l,j]
// G[b,l,j] = sum_i xu[b,i,l] * W2[((l&31)*144+i)*32 + j]
//
// R5: 1024-thread CTA (32 warps/SM, full 64k-reg file at 64 regs/thread),
// thread tile 8 batches x 2 cols, weights pre-duplicated to f32x2 in a
// prep kernel (no PACK in the hot loop). Single W2 stream per lh (no dup).
// ---------------------------------------------------------------------------

#define XS_OFF   0
#define XS_RSTR  35
#define XS_SIZE  (48*XS_RSTR*8)        // 13440 floats, 8 batches innermost
#define HS_OFF   (XS_OFF + XS_SIZE)
#define HS_SIZE  (32*32)
#define BIAS_OFF (HS_OFF + HS_SIZE)
#define BIAS_SIZE 32
#define CS_OFF   (BIAS_OFF + BIAS_SIZE)
#define CS_LSTR  68                    // per-lm: 32 G + 32 conv + 1 t + 3 pad
#define CS_BSTR  (32*CS_LSTR)
#define CS_SIZE  (8*CS_BSTR)
#define SMEM_FLOATS (CS_OFF + CS_SIZE) // 31904 floats = 127.6 KB

// duplicated weights: entry (row,cp) = float4(w[2cp],w[2cp],w[2cp+1],w[2cp+1])
__device__ float4 g_W2d[4608*16];      // rows already grouped by lm: row = lm*144+i
__device__ float4 g_kTd[144*16];       // conv, kT[i][o] = kern[o*144+i]

__global__ void prep_kernel(const float* __restrict__ kern,
                            const float* __restrict__ W2) {
    int idx = blockIdx.x * 256 + threadIdx.x;
    if (idx < 4608*16) {
        int row = idx >> 4, cp = idx & 15;
        float a = W2[row*32 + 2*cp];
        float b = W2[row*32 + 2*cp + 1];
        g_W2d[idx] = make_float4(a, a, b, b);
    } else if (idx < 4608*16 + 144*16) {
        int k = idx - 4608*16;
        int i = k >> 4, cp = k & 15;
        float a = kern[(2*cp)*144 + i];
        float b = kern[(2*cp + 1)*144 + i];
        g_kTd[k] = make_float4(a, a, b, b);
    }
}

typedef unsigned long long ull;

#define PACK2(d, s)   asm("mov.b64 %0, {%1, %1};" : "=l"(d) : "f"(s))
#define UNPACK2(lo, hi, v) asm("mov.b64 {%0, %1}, %2;" : "=f"(lo), "=f"(hi) : "l"(v))
#define FMA2(acc, a, b) asm("fma.rn.f32x2 %0, %1, %2, %0;" : "+l"(acc) : "l"(a), "l"(b))

__global__ __launch_bounds__(1024, 1)
void sca_kernel(const float* __restrict__ x, const float* __restrict__ bias,
                const float* __restrict__ cpar,
                const float* __restrict__ W1, const float* __restrict__ b1,
                const float* __restrict__ b2,
                float* __restrict__ out)
{
    extern __shared__ float sm[];
    float* xs = sm + XS_OFF;
    float* Hs = sm + HS_OFF;
    float* bs = sm + BIAS_OFF;
    float* Cs = sm + CS_OFF;

    const int tid = threadIdx.x;
    const int lh  = blockIdx.x;
    const int R   = lh >> 1;
    const int C0  = (lh & 1) * 32;

    // ---------- setup: x patch, 8 batches innermost ----------
    for (int idx = tid; idx < 8*16*3*34; idx += 1024) {
        int cc = idx % 34;
        int t2 = idx / 34;
        int kr = t2 % 3;  t2 /= 3;
        int c  = t2 % 16;
        int b  = t2 / 16;
        int r   = R - 1 + kr;
        int col = C0 - 1 + cc;
        float v = 0.f;
        if (r >= 0 && r < 64 && col >= 0 && col < 64)
            v = x[((b*16 + c)*64 + r)*64 + col];
        xs[((c*3 + kr)*XS_RSTR + cc)*8 + b] = v;
    }

    // ---------- H rows: H[o*128+lh][j], one j per thread ----------
    {
        int o = tid >> 5;
        int j = tid & 31;
        int p = o*128 + lh;
        float inp[12];
        inp[0] = (float)(p >> 6) * (1.f/64.f);
        inp[1] = 1.f - inp[0];
        inp[2] = (float)(p & 63) * (1.f/64.f);
        inp[3] = 1.f - inp[2];
        #pragma unroll
        for (int k = 0; k < 8; k++) inp[4+k] = cpar[k];
        float s = b1[j];
        #pragma unroll
        for (int k = 0; k < 12; k++) s += W1[j*12 + k] * inp[k];
        Hs[o*32 + j] = fmaxf(s, 0.f);
    }
    if (tid < 32) bs[tid] = bias[tid];
    __syncthreads();

    // ---------- main loop: 8 batches x 2 cols per thread ----------
    // tid = part*512 + lm*16 + cg
    //   part 0: G cols j = 2cg, 2cg+1  (g_W2d, L2-hot stream)
    //   part 1: conv cols o = 2cg,2cg+1 (g_kTd, L1-hot)
    {
        const int part = tid >> 9;
        const int t    = tid & 511;
        const int lm   = t >> 4;
        const int cg   = t & 15;

        const float4* wp = part ? (g_kTd + cg) : (g_W2d + lm*(144*16) + cg);
        const float* xp = xs + lm*8;

        ull acc[2][4];   // [col n][batch pair]
        #pragma unroll
        for (int n = 0; n < 2; n++)
            #pragma unroll
            for (int bp = 0; bp < 4; bp++) acc[n][bp] = 0ull;

        for (int c = 0; c < 16; ++c) {
            const float* xc = xp + c*(3*XS_RSTR*8);
            const float4* wc = wp + c*(9*16);
            #pragma unroll
            for (int kr = 0; kr < 3; ++kr) {
                #pragma unroll
                for (int kc = 0; kc < 3; ++kc) {
                    const float* xr = xc + (kr*XS_RSTR + kc)*8;
                    ulonglong2 xa = *(const ulonglong2*)(xr);      // b0..b3
                    ulonglong2 xb = *(const ulonglong2*)(xr + 4);  // b4..b7
                    ulonglong2 wd = *(const ulonglong2*)(wc + (kr*3 + kc)*16);
                    FMA2(acc[0][0], xa.x, wd.x);
                    FMA2(acc[0][1], xa.y, wd.x);
                    FMA2(acc[0][2], xb.x, wd.x);
                    FMA2(acc[0][3], xb.y, wd.x);
                    FMA2(acc[1][0], xa.x, wd.y);
                    FMA2(acc[1][1], xa.y, wd.y);
                    FMA2(acc[1][2], xb.x, wd.y);
                    FMA2(acc[1][3], xb.y, wd.y);
                }
            }
        }

        float f[8][2];
        #pragma unroll
        for (int n = 0; n < 2; n++) {
            UNPACK2(f[0][n], f[1][n], acc[n][0]);
            UNPACK2(f[2][n], f[3][n], acc[n][1]);
            UNPACK2(f[4][n], f[5][n], acc[n][2]);
            UNPACK2(f[6][n], f[7][n], acc[n][3]);
        }
        float* cb = Cs + lm*CS_LSTR + part*32 + cg*2;
        #pragma unroll
        for (int b = 0; b < 8; b++)
            *(float2*)(cb + b*CS_BSTR) = make_float2(f[b][0], f[b][1]);
    }

    // ---------- t-term tail: t[b][lm] = sum_i xu * b2[lm*144+i] ----------
    if (tid < 32) {
        int lm2 = tid;
        const float* xp2 = xs + lm2*8;
        const float* bp2 = b2 + lm2*144;
        ull ta[4] = {0ull, 0ull, 0ull, 0ull};
        for (int c = 0; c < 16; ++c) {
            #pragma unroll
            for (int kr = 0; kr < 3; ++kr) {
                #pragma unroll
                for (int kc = 0; kc < 3; ++kc) {
                    const float* xr = xp2 + (c*3*XS_RSTR + kr*XS_RSTR + kc)*8;
                    ulonglong2 xa = *(const ulonglong2*)(xr);
                    ulonglong2 xb = *(const ulonglong2*)(xr + 4);
                    ull bv; PACK2(bv, bp2[c*9 + kr*3 + kc]);
                    FMA2(ta[0], xa.x, bv); FMA2(ta[1], xa.y, bv);
                    FMA2(ta[2], xb.x, bv); FMA2(ta[3], xb.y, bv);
                }
            }
        }
        #pragma unroll
        for (int bp = 0; bp < 4; bp++) {
            float lo, hi; UNPACK2(lo, hi, ta[bp]);
            Cs[(2*bp)*CS_BSTR   + lm2*CS_LSTR + 64] = lo;
            Cs[(2*bp+1)*CS_BSTR + lm2*CS_LSTR + 64] = hi;
        }
    }
    __syncthreads();

    // ---------- epilogue: out = bias + t + conv + H·G ----------
    {
        int b   = tid >> 7;            // 0..7
        int oq  = (tid >> 5) & 3;      // o = oq*8 .. +7
        int lm3 = tid & 31;            // lanes = consecutive lm -> coalesced
        const float* cb = Cs + b*CS_BSTR + lm3*CS_LSTR;

        float g[32];
        #pragma unroll
        for (int q = 0; q < 8; q++) {
            float4 v = *(const float4*)(cb + q*4);
            g[q*4+0] = v.x; g[q*4+1] = v.y; g[q*4+2] = v.z; g[q*4+3] = v.w;
        }
        float cw[8];
        #pragma unroll
        for (int q = 0; q < 2; q++) {
            float4 v = *(const float4*)(cb + 32 + oq*8 + q*4);
            cw[q*4+0] = v.x; cw[q*4+1] = v.y; cw[q*4+2] = v.z; cw[q*4+3] = v.w;
        }
        float tv = cb[64];

        float* ob = out + b*(32*4096) + (oq*8)*4096 + lh*32 + lm3;
        #pragma unroll
        for (int oo = 0; oo < 8; oo++) {
            int o = oq*8 + oo;
            float s = bs[o] + tv + cw[oo];
            const float4* h4 = (const float4*)(Hs + o*32);
            #pragma unroll
            for (int q = 0; q < 8; q++) {
                float4 h = h4[q];
                s += h.x*g[q*4] + h.y*g[q*4+1] + h.z*g[q*4+2] + h.w*g[q*4+3];
            }
            ob[oo*4096] = s;
        }
    }
}

extern "C" void kernel_launch(void* const* d_in, const int* in_sizes, int n_in,
                              void* d_out, int out_size)
{
    const float* x    = (const float*)d_in[0];   // (8,16,64,64)
    const float* kern = (const float*)d_in[1];   // (32,144)
    const float* bias = (const float*)d_in[2];   // (32,)
    const float* cpar = (const float*)d_in[3];   // (1,8)
    const float* W1   = (const float*)d_in[4];   // (32,12)
    const float* b1   = (const float*)d_in[5];   // (32,)
    const float* W2   = (const float*)d_in[6];   // (4608,32)
    const float* b2   = (const float*)d_in[7];   // (4608,)
    float* out = (float*)d_out;                  // (8,32,64,64)

    prep_kernel<<<297, 256>>>(kern, W2);
    cudaFuncSetAttribute(sca_kernel, cudaFuncAttributeMaxDynamicSharedMemorySize,
                         SMEM_FLOATS * 4);
    sca_kernel<<<128, 1024, SMEM_FLOATS * 4>>>(x, bias, cpar, W1, b1, b2, out);
}

// round 7
// speedup vs baseline: 1.4517x; 1.4517x over previous
#include <cuda_runtime.h>
#include <cstdint>

// ---------------------------------------------------------------------------
// SCAConv decomposition (same math as R2-R5):
// out[b,o,l] = bias[o] + sum_i xu*kernel[o,i] + sum_i xu*b2[(l&31)*144+i]
//            + sum_j H[o*128+(l>>5), j] * G[b,l,j]
// G[b,l,j] = sum_i xu[b,i,l] * W2[((l&31)*144+i)*32 + j]
//
// R6 = R3 (best: 512thr, 8b x 4c f32x2 tile, 104 regs) +
//   (a) #pragma unroll 4 on the c-loop -> deep MLP on the W2 LDG stream
//   (b) t-term distributed over all 512 threads (was 1 warp, serial tail)
// ---------------------------------------------------------------------------

#define XS_OFF   0
#define XS_RSTR  35
#define XS_SIZE  (48*XS_RSTR*8)        // 13440 floats, batch innermost
#define HS_OFF   (XS_OFF + XS_SIZE)
#define HS_SIZE  (32*32)
#define BIAS_OFF (HS_OFF + HS_SIZE)
#define BIAS_SIZE 32
#define CS_OFF   (BIAS_OFF + BIAS_SIZE)
#define CS_LSTR  68                    // per-lm: 32 G + 32 conv + 2 t-halves + 2 pad
#define CS_BSTR  (32*CS_LSTR)
#define CS_SIZE  (8*CS_BSTR)
#define SMEM_FLOATS (CS_OFF + CS_SIZE) // 31904 floats = 127.6 KB

__device__ float g_kT[144*32];         // kernel transposed: kT[i][o]

__global__ void prep_kernel(const float* __restrict__ kern) {
    int idx = blockIdx.x * 256 + threadIdx.x;
    if (idx < 4608) {
        int i = idx >> 5, o = idx & 31;
        g_kT[idx] = kern[o*144 + i];
    }
}

typedef unsigned long long ull;

#define PACK2(d, s)   asm("mov.b64 %0, {%1, %1};" : "=l"(d) : "f"(s))
#define UNPACK2(lo, hi, v) asm("mov.b64 {%0, %1}, %2;" : "=f"(lo), "=f"(hi) : "l"(v))
#define FMA2(acc, a, b) asm("fma.rn.f32x2 %0, %1, %2, %0;" : "+l"(acc) : "l"(a), "l"(b))

__global__ __launch_bounds__(512, 1)
void sca_kernel(const float* __restrict__ x, const float* __restrict__ bias,
                const float* __restrict__ cpar,
                const float* __restrict__ W1, const float* __restrict__ b1,
                const float* __restrict__ W2, const float* __restrict__ b2,
                float* __restrict__ out)
{
    extern __shared__ float sm[];
    float* xs = sm + XS_OFF;
    float* Hs = sm + HS_OFF;
    float* bs = sm + BIAS_OFF;
    float* Cs = sm + CS_OFF;

    const int tid = threadIdx.x;
    const int lh  = blockIdx.x;
    const int R   = lh >> 1;
    const int C0  = (lh & 1) * 32;

    // ---------- setup: x patch, batch-innermost ----------
    for (int idx = tid; idx < 8*16*3*34; idx += 512) {
        int cc = idx % 34;
        int t2 = idx / 34;
        int kr = t2 % 3;  t2 /= 3;
        int c  = t2 % 16;
        int b  = t2 / 16;
        int r   = R - 1 + kr;
        int col = C0 - 1 + cc;
        float v = 0.f;
        if (r >= 0 && r < 64 && col >= 0 && col < 64)
            v = x[((b*16 + c)*64 + r)*64 + col];
        xs[((c*3 + kr)*XS_RSTR + cc)*8 + b] = v;
    }

    // ---------- H rows: H[o*128+lh][j] ----------
    {
        int o  = tid >> 4;
        int jh = tid & 15;
        int p  = o*128 + lh;
        float inp[12];
        inp[0] = (float)(p >> 6) * (1.f/64.f);
        inp[1] = 1.f - inp[0];
        inp[2] = (float)(p & 63) * (1.f/64.f);
        inp[3] = 1.f - inp[2];
        #pragma unroll
        for (int k = 0; k < 8; k++) inp[4+k] = cpar[k];
        #pragma unroll
        for (int jj = 0; jj < 2; jj++) {
            int j = jh*2 + jj;
            float s = b1[j];
            #pragma unroll
            for (int k = 0; k < 12; k++) s += W1[j*12 + k] * inp[k];
            Hs[o*32 + j] = fmaxf(s, 0.f);
        }
    }
    if (tid < 32) bs[tid] = bias[tid];
    __syncthreads();

    // ---------- main loop: 8 batches x 4 cols per thread, f32x2 packed ----------
    // tid = part*256 + lm*8 + cg ; part 0: G cols j = cg*4..+3 (W2, L2-hot)
    //                              part 1: conv cols o = cg*4..+3 (g_kT, L1-hot)
    {
        const int part = tid >> 8;
        const int t    = tid & 255;
        const int lm   = t >> 3;
        const int cg   = t & 7;

        const float* wp = part ? (g_kT + cg*4) : (W2 + lm*4608 + cg*4);
        const float* xp = xs + lm*8;

        ull acc[4][4];   // [col n][batch pair bp]
        #pragma unroll
        for (int n = 0; n < 4; n++)
            #pragma unroll
            for (int bp = 0; bp < 4; bp++) acc[n][bp] = 0ull;

        #pragma unroll 4
        for (int c = 0; c < 16; ++c) {
            const float* xc = xp + c*(3*XS_RSTR*8);
            const float* wc = wp + c*(9*32);
            #pragma unroll
            for (int kr = 0; kr < 3; ++kr) {
                #pragma unroll
                for (int kc = 0; kc < 3; ++kc) {
                    const float* xr = xc + (kr*XS_RSTR + kc)*8;
                    ulonglong2 xa = *(const ulonglong2*)(xr);      // b0..b3
                    ulonglong2 xb = *(const ulonglong2*)(xr + 4);  // b4..b7
                    float4 w = *(const float4*)(wc + (kr*3 + kc)*32);
                    ull wpk[4];
                    PACK2(wpk[0], w.x); PACK2(wpk[1], w.y);
                    PACK2(wpk[2], w.z); PACK2(wpk[3], w.w);
                    #pragma unroll
                    for (int n = 0; n < 4; n++) {
                        FMA2(acc[n][0], xa.x, wpk[n]);
                        FMA2(acc[n][1], xa.y, wpk[n]);
                        FMA2(acc[n][2], xb.x, wpk[n]);
                        FMA2(acc[n][3], xb.y, wpk[n]);
                    }
                }
            }
        }

        // unpack -> per-batch float4 stores
        float f[8][4];
        #pragma unroll
        for (int n = 0; n < 4; n++)
            #pragma unroll
            for (int bp = 0; bp < 4; bp++)
                UNPACK2(f[2*bp][n], f[2*bp+1][n], acc[n][bp]);
        float* cb = Cs + lm*CS_LSTR + part*32 + cg*4;
        #pragma unroll
        for (int b = 0; b < 8; b++)
            *(float4*)(cb + b*CS_BSTR) = make_float4(f[b][0], f[b][1], f[b][2], f[b][3]);
    }

    // ---------- t-term, distributed: 256 (b,lm) outputs x 2 i-halves ----------
    {
        const int half = tid >> 8;         // 0/1: c in [half*8, half*8+8)
        const int idx  = tid & 255;
        const int b    = idx & 7;
        const int lm2  = idx >> 3;
        const float* bp2 = b2 + lm2*144;
        float tacc = 0.f;
        #pragma unroll 2
        for (int c = half*8; c < half*8 + 8; ++c) {
            #pragma unroll
            for (int kr = 0; kr < 3; ++kr) {
                #pragma unroll
                for (int kc = 0; kc < 3; ++kc) {
                    float xv = xs[((c*3 + kr)*XS_RSTR + lm2 + kc)*8 + b];
                    tacc += xv * bp2[c*9 + kr*3 + kc];
                }
            }
        }
        Cs[b*CS_BSTR + lm2*CS_LSTR + 64 + half] = tacc;
    }
    __syncthreads();

    // ---------- epilogue: out = bias + t + conv + H·G ----------
    {
        int b   = tid >> 6;
        int oh  = (tid >> 5) & 1;
        int lm3 = tid & 31;
        const float* cb = Cs + b*CS_BSTR + lm3*CS_LSTR;

        float g[32];
        #pragma unroll
        for (int q = 0; q < 8; q++) {
            float4 v = *(const float4*)(cb + q*4);
            g[q*4+0] = v.x; g[q*4+1] = v.y; g[q*4+2] = v.z; g[q*4+3] = v.w;
        }
        float cw[16];
        #pragma unroll
        for (int q = 0; q < 4; q++) {
            float4 v = *(const float4*)(cb + 32 + oh*16 + q*4);
            cw[q*4+0] = v.x; cw[q*4+1] = v.y; cw[q*4+2] = v.z; cw[q*4+3] = v.w;
        }
        float tv = cb[64] + cb[65];

        float* ob = out + b*(32*4096) + (oh*16)*4096 + lh*32 + lm3;
        #pragma unroll
        for (int oo = 0; oo < 16; oo++) {
            int o = oh*16 + oo;
            float s = bs[o] + tv + cw[oo];
            const float4* h4 = (const float4*)(Hs + o*32);
            #pragma unroll
            for (int q = 0; q < 8; q++) {
                float4 h = h4[q];
                s += h.x*g[q*4] + h.y*g[q*4+1] + h.z*g[q*4+2] + h.w*g[q*4+3];
            }
            ob[oo*4096] = s;
        }
    }
}

extern "C" void kernel_launch(void* const* d_in, const int* in_sizes, int n_in,
                              void* d_out, int out_size)
{
    const float* x    = (const float*)d_in[0];   // (8,16,64,64)
    const float* kern = (const float*)d_in[1];   // (32,144)
    const float* bias = (const float*)d_in[2];   // (32,)
    const float* cpar = (const float*)d_in[3];   // (1,8)
    const float* W1   = (const float*)d_in[4];   // (32,12)
    const float* b1   = (const float*)d_in[5];   // (32,)
    const float* W2   = (const float*)d_in[6];   // (4608,32)
    const float* b2   = (const float*)d_in[7];   // (4608,)
    float* out = (float*)d_out;                  // (8,32,64,64)

    prep_kernel<<<18, 256>>>(kern);
    cudaFuncSetAttribute(sca_kernel, cudaFuncAttributeMaxDynamicSharedMemorySize,
                         SMEM_FLOATS * 4);
    sca_kernel<<<128, 512, SMEM_FLOATS * 4>>>(x, bias, cpar, W1, b1, W2, b2, out);
}